// round 14
// baseline (speedup 1.0000x reference)
#include <cuda_runtime.h>
#include <cuda_bf16.h>
#include <math.h>
#include <stdint.h>

#define Bb 2
#define Ss 2048
#define HIDD 2048
#define NKH 16
#define NVH 32
#define DKD 128
#define DVD 128
#define KEY_DIM 2048
#define VAL_DIM 4096
#define CONV_DIM 8192

// ---------------- fp32 scratch ---------------------------------------------------
__device__ float g_mixed[(size_t)Bb * Ss * CONV_DIM];   // qkv projection (pre-conv)
__device__ float g_conv [(size_t)Bb * Ss * CONV_DIM];   // conv+silu output; q,k normalized in-place
__device__ float g_z    [(size_t)Bb * Ss * VAL_DIM];    // gate branch
__device__ float g_o    [(size_t)Bb * Ss * VAL_DIM];    // recurrence output, gated in-place
__device__ float g_beta [Bb * Ss * NVH];
__device__ float g_dec  [Bb * Ss * NVH];                // log-decay g

// ---------------- bf16x3 split scratch: A' = [Ah|Al|Ah], B' = [Bh|Bh|Bl] ---------
__device__ __nv_bfloat16 g_hs3[(size_t)4096 * 3 * 2048];   // hidden_states  (A-mode)
__device__ __nv_bfloat16 g_wq3[(size_t)8192 * 3 * 2048];   // W_qkv          (B-mode)
__device__ __nv_bfloat16 g_wz3[(size_t)4096 * 3 * 2048];   // W_z            (B-mode)
__device__ __nv_bfloat16 g_wo3[(size_t)2048 * 3 * 4096];   // W_out          (B-mode)
__device__ __nv_bfloat16 g_go3[(size_t)4096 * 3 * 4096];   // gated output   (A-mode)

// ---------------- fp32 [R][K] -> bf16 [R][3K] split ------------------------------
// amode=1: [hi | lo | hi]   amode=0 (B): [hi | hi | lo]
__global__ __launch_bounds__(256) void cvt3(
    const float* __restrict__ x, __nv_bfloat16* __restrict__ y,
    int K, int n4, int amode)
{
    int i = blockIdx.x * 256 + threadIdx.x;
    if (i >= n4) return;
    int e = i * 4;
    int r = e / K;
    int k = e - r * K;
    float4 v = *(const float4*)(x + (size_t)e);
    __nv_bfloat16 h0 = __float2bfloat16(v.x), h1 = __float2bfloat16(v.y);
    __nv_bfloat16 h2 = __float2bfloat16(v.z), h3 = __float2bfloat16(v.w);
    __nv_bfloat16 l0 = __float2bfloat16(v.x - __bfloat162float(h0));
    __nv_bfloat16 l1 = __float2bfloat16(v.y - __bfloat162float(h1));
    __nv_bfloat16 l2 = __float2bfloat16(v.z - __bfloat162float(h2));
    __nv_bfloat16 l3 = __float2bfloat16(v.w - __bfloat162float(h3));
    __nv_bfloat162 H0(h0, h1), H1(h2, h3), L0(l0, l1), L1(l2, l3);
    __nv_bfloat162* row = (__nv_bfloat162*)(y + (size_t)r * 3 * K);
    int kq = k >> 1;
    int K2 = K >> 1;
    row[kq] = H0; row[kq + 1] = H1;                       // seg 0: hi
    if (amode) {
        row[K2 + kq] = L0;     row[K2 + kq + 1] = L1;     // seg 1: lo
        row[2 * K2 + kq] = H0; row[2 * K2 + kq + 1] = H1; // seg 2: hi
    } else {
        row[K2 + kq] = H0;     row[K2 + kq + 1] = H1;     // seg 1: hi
        row[2 * K2 + kq] = L0; row[2 * K2 + kq + 1] = L1; // seg 2: lo
    }
}

// ---------------- bf16 mma.sync GEMM: C[M,N] = A[M,Kd] * B[N,Kd]^T ----------------
__device__ __forceinline__ uint32_t s2u(const void* p) {
    uint32_t a;
    asm("{ .reg .u64 t; cvta.to.shared.u64 t, %1; cvt.u32.u64 %0, t; }" : "=r"(a) : "l"(p));
    return a;
}

#define NSTAGE 4
#define ROWP 40                               // padded smem row: 40 bf16 = 80 B
#define STAGE_BYTES (128 * ROWP * 2)          // 10240
#define GEMM_SMEM (2 * NSTAGE * STAGE_BYTES)  // 81920

__device__ __forceinline__ void cp16(uint32_t s, const void* g) {
    asm volatile("cp.async.cg.shared.global [%0], [%1], 16;" :: "r"(s), "l"(g) : "memory");
}
__device__ __forceinline__ void ldmx4(uint32_t* r, uint32_t addr) {
    asm volatile("ldmatrix.sync.aligned.m8n8.x4.shared.b16 {%0,%1,%2,%3}, [%4];"
                 : "=r"(r[0]), "=r"(r[1]), "=r"(r[2]), "=r"(r[3]) : "r"(addr));
}
__device__ __forceinline__ void mma16816(float* d, const uint32_t* a, const uint32_t* b) {
    asm volatile(
        "mma.sync.aligned.m16n8k16.row.col.f32.bf16.bf16.f32 "
        "{%0,%1,%2,%3}, {%4,%5,%6,%7}, {%8,%9}, {%0,%1,%2,%3};"
        : "+f"(d[0]), "+f"(d[1]), "+f"(d[2]), "+f"(d[3])
        : "r"(a[0]), "r"(a[1]), "r"(a[2]), "r"(a[3]), "r"(b[0]), "r"(b[1]));
}

__global__ __launch_bounds__(256) void gemm_mma(
    const __nv_bfloat16* __restrict__ A, const __nv_bfloat16* __restrict__ B,
    float* __restrict__ C, int N, int Kd)
{
    extern __shared__ char dsm[];
    const uint32_t sb = s2u(dsm);
    const uint32_t sA = sb, sB = sb + NSTAGE * STAGE_BYTES;
    const int tid = threadIdx.x, lane = tid & 31, wid = tid >> 5;
    const int wm = wid & 1, wn = wid >> 1;        // warp grid 2 x 4
    const int rowB = blockIdx.y * 128, colB = blockIdx.x * 128;

    // ---- loader mapping: thread -> (row, 16-element half of a 32-elem k-chunk)
    const int lr = tid >> 1;
    const int ls = (tid & 1) * 16;                // element offset 0 / 16
    const __nv_bfloat16* gA = A + (size_t)(rowB + lr) * Kd + ls;
    const __nv_bfloat16* gB = B + (size_t)(colB + lr) * Kd + ls;
    const uint32_t smA = sA + (uint32_t)(lr * ROWP + ls) * 2;
    const uint32_t smB = sB + (uint32_t)(lr * ROWP + ls) * 2;

    // ---- ldmatrix per-lane address components
    const int mid = lane >> 3;                    // matrix id 0..3
    const int aRow = (lane & 7) + ((mid & 1) << 3);
    const int aK   = (mid >> 1) << 3;
    const uint32_t aBase = sA + (uint32_t)((wm * 64 + aRow) * ROWP + aK) * 2;
    const int bN = ((mid >> 1) << 3) + (lane & 7);
    const int bK = (mid & 1) << 3;
    const uint32_t bBase = sB + (uint32_t)((wn * 32 + bN) * ROWP + bK) * 2;

    float acc[4][4][4];
#pragma unroll
    for (int i = 0; i < 4; i++)
#pragma unroll
        for (int j = 0; j < 4; j++)
#pragma unroll
            for (int q = 0; q < 4; q++) acc[i][j][q] = 0.f;

    auto load_stage = [&](int kt) {
        uint32_t off = (uint32_t)(kt & (NSTAGE - 1)) * STAGE_BYTES;
        const __nv_bfloat16* pa = gA + (size_t)kt * 32;
        const __nv_bfloat16* pb = gB + (size_t)kt * 32;
        cp16(smA + off, pa);      cp16(smA + off + 16, pa + 8);
        cp16(smB + off, pb);      cp16(smB + off + 16, pb + 8);
    };

    const int NT = Kd >> 5;                       // k32 chunks
    load_stage(0); asm volatile("cp.async.commit_group;" ::: "memory");
    load_stage(1); asm volatile("cp.async.commit_group;" ::: "memory");
    load_stage(2); asm volatile("cp.async.commit_group;" ::: "memory");

    for (int kt = 0; kt < NT; kt++) {
        asm volatile("cp.async.wait_group 2;" ::: "memory");
        __syncthreads();
        // refill stage (kt+3)&3 == (kt-1)&3: consumed by all warps in iter kt-1,
        // guaranteed complete chip-wide by the barrier above.
        if (kt + 3 < NT) load_stage(kt + 3);
        asm volatile("cp.async.commit_group;" ::: "memory");

        const uint32_t soff = (uint32_t)(kt & (NSTAGE - 1)) * STAGE_BYTES;
#pragma unroll
        for (int kh = 0; kh < 2; kh++) {
            uint32_t ra[4][4], rb[2][4];
#pragma unroll
            for (int mt = 0; mt < 4; mt++)
                ldmx4(ra[mt], aBase + soff + (uint32_t)(mt * 16 * ROWP * 2) + kh * 32);
#pragma unroll
            for (int np = 0; np < 2; np++)
                ldmx4(rb[np], bBase + soff + (uint32_t)(np * 16 * ROWP * 2) + kh * 32);
#pragma unroll
            for (int mt = 0; mt < 4; mt++)
#pragma unroll
                for (int nt = 0; nt < 4; nt++)
                    mma16816(acc[mt][nt], ra[mt], &rb[nt >> 1][(nt & 1) * 2]);
        }
    }

    // ---- epilogue: fp32 store
    const int erow = rowB + wm * 64 + (lane >> 2);
    const int ecol = colB + wn * 32 + (lane & 3) * 2;
#pragma unroll
    for (int mt = 0; mt < 4; mt++) {
#pragma unroll
        for (int nt = 0; nt < 4; nt++) {
            float* p0 = C + (size_t)(erow + mt * 16) * N + ecol + nt * 8;
            *(float2*)p0                    = make_float2(acc[mt][nt][0], acc[mt][nt][1]);
            *(float2*)(p0 + (size_t)8 * N)  = make_float2(acc[mt][nt][2], acc[mt][nt][3]);
        }
    }
}

// ---------------- causal depthwise conv (K=4) + silu ----------------------------
__global__ __launch_bounds__(256) void conv_silu(const float* __restrict__ w)
{
    size_t idx = (size_t)blockIdx.x * 256 + threadIdx.x;
    int c = (int)(idx & (CONV_DIM - 1));
    size_t bs = idx >> 13;
    int s = (int)(bs & (Ss - 1));
    const float* col = g_mixed + idx;
    float4 wv = *(const float4*)(w + (size_t)c * 4);
    float acc = wv.w * col[0];
    if (s >= 1) acc += wv.z * col[-(ptrdiff_t)CONV_DIM];
    if (s >= 2) acc += wv.y * col[-(ptrdiff_t)2 * CONV_DIM];
    if (s >= 3) acc += wv.x * col[-(ptrdiff_t)3 * CONV_DIM];
    g_conv[idx] = acc / (1.f + expf(-acc));
}

// ---------------- l2-normalize q,k heads in-place (q also gets DK^-0.5) ---------
__global__ __launch_bounds__(128) void l2norm_qk()
{
    int g = blockIdx.x & 31;
    size_t row = blockIdx.x >> 5;
    float* p = g_conv + row * CONV_DIM + (size_t)g * 128;
    float v = p[threadIdx.x];
    float ss = v * v;
    __shared__ float sh[4];
#pragma unroll
    for (int o = 16; o; o >>= 1) ss += __shfl_down_sync(0xffffffffu, ss, o);
    if ((threadIdx.x & 31) == 0) sh[threadIdx.x >> 5] = ss;
    __syncthreads();
    float tot = sh[0] + sh[1] + sh[2] + sh[3];
    float r = rsqrtf(tot + 1e-6f);
    if (g < 16) r *= 0.08838834764831845f;
    p[threadIdx.x] = v * r;
}

// ---------------- b/a projections -> beta, log-decay g --------------------------
__global__ __launch_bounds__(128) void proj_bg(
    const float* __restrict__ hs, const float* __restrict__ Wb,
    const float* __restrict__ Wa, const float* __restrict__ dtb,
    const float* __restrict__ Alog)
{
    __shared__ float sh[HIDD];
    size_t row = blockIdx.x;
    const float* hr = hs + row * HIDD;
    for (int i = threadIdx.x; i < HIDD; i += 128) sh[i] = hr[i];
    __syncthreads();
    int warp = threadIdx.x >> 5, lane = threadIdx.x & 31;
    for (int i = 0; i < 16; i++) {
        int o = warp * 16 + i;
        const float* w = (o < 32) ? (Wb + (size_t)o * HIDD) : (Wa + (size_t)(o - 32) * HIDD);
        float s = 0.f;
        for (int k2 = lane; k2 < HIDD; k2 += 32) s += sh[k2] * w[k2];
#pragma unroll
        for (int off = 16; off; off >>= 1) s += __shfl_down_sync(0xffffffffu, s, off);
        if (lane == 0) {
            if (o < 32) {
                g_beta[row * NVH + o] = 1.f / (1.f + expf(-s));
            } else {
                int h = o - 32;
                float x = s + dtb[h];
                float sp = (x > 20.f) ? x : log1pf(expf(x));
                g_dec[row * NVH + h] = -expf(Alog[h]) * sp;
            }
        }
    }
}

// ---------------- gated delta-rule recurrence (sequential in t) -----------------
__global__ __launch_bounds__(128) void recurrence()
{
    const int blk = blockIdx.x;
    const int vh  = blk & 1;
    const int h   = (blk >> 1) & 31;
    const int b   = blk >> 6;
    const int hk  = h >> 1;
    const int tid = threadIdx.x;
    const int dkh = tid >> 6;
    const int dvl = tid & 63;
    const int dv  = vh * 64 + dvl;
    const int dk0 = dkh * 64;

    __shared__ float sq[128], sk[128], redA[128], redB[128];
    __shared__ float sgb[2];

    float st[64];
#pragma unroll
    for (int i = 0; i < 64; i++) st[i] = 0.f;

    const float* qb = g_conv + (size_t)b * Ss * CONV_DIM + hk * 128;
    const float* kb = qb + KEY_DIM;
    const float* vb = g_conv + (size_t)b * Ss * CONV_DIM + 2 * KEY_DIM + h * 128 + dv;
    float*       ob = g_o    + (size_t)b * Ss * VAL_DIM + h * 128 + dv;
    const float* gp = g_dec  + (size_t)b * Ss * NVH + h;
    const float* bp = g_beta + (size_t)b * Ss * NVH + h;

    for (int t = 0; t < Ss; t++) {
        size_t off = (size_t)t * CONV_DIM;
        sq[tid] = qb[off + tid];
        sk[tid] = kb[off + tid];
        if (tid == 0) sgb[0] = gp[(size_t)t * NVH];
        if (tid == 1) sgb[1] = bp[(size_t)t * NVH];
        float v = vb[off];
        __syncthreads();
        float eg  = expf(sgb[0]);
        float bet = sgb[1];

        float m0 = 0.f, m1 = 0.f, m2 = 0.f, m3 = 0.f;
#pragma unroll
        for (int i = 0; i < 64; i += 4) {
            float s0 = st[i]     * eg;
            float s1 = st[i + 1] * eg;
            float s2 = st[i + 2] * eg;
            float s3 = st[i + 3] * eg;
            st[i] = s0; st[i + 1] = s1; st[i + 2] = s2; st[i + 3] = s3;
            m0 += sk[dk0 + i]     * s0;
            m1 += sk[dk0 + i + 1] * s1;
            m2 += sk[dk0 + i + 2] * s2;
            m3 += sk[dk0 + i + 3] * s3;
        }
        redA[tid] = (m0 + m1) + (m2 + m3);
        __syncthreads();
        float mem   = redA[tid] + redA[tid ^ 64];
        float delta = (v - mem) * bet;

        float o0 = 0.f, o1 = 0.f, o2 = 0.f, o3 = 0.f;
#pragma unroll
        for (int i = 0; i < 64; i += 4) {
            float s0 = st[i]     + sk[dk0 + i]     * delta;
            float s1 = st[i + 1] + sk[dk0 + i + 1] * delta;
            float s2 = st[i + 2] + sk[dk0 + i + 2] * delta;
            float s3 = st[i + 3] + sk[dk0 + i + 3] * delta;
            st[i] = s0; st[i + 1] = s1; st[i + 2] = s2; st[i + 3] = s3;
            o0 += sq[dk0 + i]     * s0;
            o1 += sq[dk0 + i + 1] * s1;
            o2 += sq[dk0 + i + 2] * s2;
            o3 += sq[dk0 + i + 3] * s3;
        }
        redB[tid] = (o0 + o1) + (o2 + o3);
        __syncthreads();
        if (dkh == 0) ob[(size_t)t * VAL_DIM] = redB[tid] + redB[tid ^ 64];
    }
}

// ---------------- gated RMSNorm: o = o*rsqrt(mean(o^2)+eps)*w * silu(z) ---------
__global__ __launch_bounds__(128) void gate_norm(const float* __restrict__ nw)
{
    size_t row = blockIdx.x;
    float* op = g_o + row * DVD;
    const float* zp = g_z + row * DVD;
    float v = op[threadIdx.x];
    float ss = v * v;
    __shared__ float sh[4];
#pragma unroll
    for (int o = 16; o; o >>= 1) ss += __shfl_down_sync(0xffffffffu, ss, o);
    if ((threadIdx.x & 31) == 0) sh[threadIdx.x >> 5] = ss;
    __syncthreads();
    float var = (sh[0] + sh[1] + sh[2] + sh[3]) * (1.f / DVD);
    float r = rsqrtf(var + 1e-6f);
    float z = zp[threadIdx.x];
    float sz = z / (1.f + expf(-z));
    op[threadIdx.x] = v * r * nw[threadIdx.x] * sz;
}

// ---------------- launch ---------------------------------------------------------
extern "C" void kernel_launch(void* const* d_in, const int* in_sizes, int n_in,
                              void* d_out, int out_size)
{
    const float* hs   = (const float*)d_in[0];
    const float* Wqkv = (const float*)d_in[1];
    const float* Wz   = (const float*)d_in[2];
    const float* Wb   = (const float*)d_in[3];
    const float* Wa   = (const float*)d_in[4];
    const float* cw   = (const float*)d_in[5];
    const float* nw   = (const float*)d_in[6];
    const float* Wout = (const float*)d_in[7];
    const float* dtb  = (const float*)d_in[8];
    const float* Alog = (const float*)d_in[9];
    float* out = (float*)d_out;

    float *mixed, *zb, *ob;
    __nv_bfloat16 *hs3, *wq3, *wz3, *wo3, *go3;
    cudaGetSymbolAddress((void**)&mixed, g_mixed);
    cudaGetSymbolAddress((void**)&zb,    g_z);
    cudaGetSymbolAddress((void**)&ob,    g_o);
    cudaGetSymbolAddress((void**)&hs3, g_hs3);
    cudaGetSymbolAddress((void**)&wq3, g_wq3);
    cudaGetSymbolAddress((void**)&wz3, g_wz3);
    cudaGetSymbolAddress((void**)&wo3, g_wo3);
    cudaGetSymbolAddress((void**)&go3, g_go3);

    cudaFuncSetAttribute(gemm_mma, cudaFuncAttributeMaxDynamicSharedMemorySize, GEMM_SMEM);

    const int M = Bb * Ss;                                  // 4096

    // 0. bf16x3 splits (A-mode: [h|l|h], B-mode: [h|h|l])
    cvt3<<<(M * HIDD / 4 + 255) / 256, 256>>>(hs, hs3, HIDD, M * HIDD / 4, 1);
    cvt3<<<(CONV_DIM * HIDD / 4 + 255) / 256, 256>>>(Wqkv, wq3, HIDD, CONV_DIM * HIDD / 4, 0);
    cvt3<<<(VAL_DIM * HIDD / 4 + 255) / 256, 256>>>(Wz, wz3, HIDD, VAL_DIM * HIDD / 4, 0);
    cvt3<<<(HIDD * VAL_DIM / 4 + 255) / 256, 256>>>(Wout, wo3, VAL_DIM, HIDD * VAL_DIM / 4, 0);

    // 1. qkv projection: [M,3*HID] x [CONV_DIM,3*HID]^T (HMMA)
    gemm_mma<<<dim3(CONV_DIM / 128, M / 128), 256, GEMM_SMEM>>>(
        hs3, wq3, mixed, CONV_DIM, 3 * HIDD);
    // 2. gate branch z
    gemm_mma<<<dim3(VAL_DIM / 128, M / 128), 256, GEMM_SMEM>>>(
        hs3, wz3, zb, VAL_DIM, 3 * HIDD);
    // 3. beta / log-decay
    proj_bg<<<M, 128>>>(hs, Wb, Wa, dtb, Alog);
    // 4. causal depthwise conv + silu
    conv_silu<<<(Bb * Ss * CONV_DIM) / 256, 256>>>(cw);
    // 5. l2norm q,k (q scaled by DK^-0.5)
    l2norm_qk<<<Bb * Ss * 32, 128>>>();
    // 6. sequential delta-rule recurrence
    recurrence<<<Bb * NVH * 2, 128>>>();
    // 7. gated RMSNorm (in-place on g_o)
    gate_norm<<<Bb * Ss * NVH, 128>>>(nw);
    // 8. split gated output, then output projection (HMMA) -> d_out
    cvt3<<<(M * VAL_DIM / 4 + 255) / 256, 256>>>(ob, go3, VAL_DIM, M * VAL_DIM / 4, 1);
    gemm_mma<<<dim3(HIDD / 128, M / 128), 256, GEMM_SMEM>>>(
        go3, wo3, out, HIDD, 3 * VAL_DIM);
}

// round 15
// speedup vs baseline: 1.0531x; 1.0531x over previous
#include <cuda_runtime.h>
#include <cuda_fp16.h>
#include <math.h>
#include <stdint.h>

#define Bb 2
#define Ss 2048
#define HIDD 2048
#define NKH 16
#define NVH 32
#define DKD 128
#define DVD 128
#define KEY_DIM 2048
#define VAL_DIM 4096
#define CONV_DIM 8192

// ---------------- fp32 scratch ---------------------------------------------------
__device__ float g_mixed[(size_t)Bb * Ss * CONV_DIM];
__device__ float g_conv [(size_t)Bb * Ss * CONV_DIM];
__device__ float g_z    [(size_t)Bb * Ss * VAL_DIM];
__device__ float g_o    [(size_t)Bb * Ss * VAL_DIM];
__device__ float g_beta [Bb * Ss * NVH];
__device__ float g_dec  [Bb * Ss * NVH];

// ---------------- fp16 split scratch ---------------------------------------------
__device__ __half g_hs3[(size_t)4096 * 3 * 2048];   // hidden_states [h|l|h]  (GEMM1 A)
__device__ __half g_wq3[(size_t)8192 * 3 * 2048];   // W_qkv         [h|h|l]  (GEMM1 B)
__device__ __half g_hs2[(size_t)4096 * 2 * 2048];   // hidden_states [h|l]    (GEMM2 A)
__device__ __half g_wz2[(size_t)4096 * 2 * 2048];   // W_z           [h|h]    (GEMM2 B)
__device__ __half g_wo2[(size_t)2048 * 2 * 4096];   // W_out         [h|h]    (GEMM3 B)
__device__ __half g_go2[(size_t)4096 * 2 * 4096];   // gated output  [h|l]    (GEMM3 A)

// ---------------- fp32 [R][K] -> fp16 [R][3K] split -------------------------------
// amode=1 (A): [hi | lo | hi]   amode=0 (B): [hi | hi | lo]
__global__ __launch_bounds__(256) void cvt3(
    const float* __restrict__ x, __half* __restrict__ y, int K, int n4, int amode)
{
    int i = blockIdx.x * 256 + threadIdx.x;
    if (i >= n4) return;
    int e = i * 4;
    int r = e / K;
    int k = e - r * K;
    float4 v = *(const float4*)(x + (size_t)e);
    __half h0 = __float2half(v.x), h1 = __float2half(v.y);
    __half h2 = __float2half(v.z), h3 = __float2half(v.w);
    __half2 H0 = __halves2half2(h0, h1), H1 = __halves2half2(h2, h3);
    __half2 L0 = __halves2half2(__float2half(v.x - __half2float(h0)),
                                __float2half(v.y - __half2float(h1)));
    __half2 L1 = __halves2half2(__float2half(v.z - __half2float(h2)),
                                __float2half(v.w - __half2float(h3)));
    __half2* row = (__half2*)(y + (size_t)r * 3 * K);
    int kq = k >> 1, K2 = K >> 1;
    row[kq] = H0; row[kq + 1] = H1;
    if (amode) {
        row[K2 + kq] = L0;     row[K2 + kq + 1] = L1;
        row[2 * K2 + kq] = H0; row[2 * K2 + kq + 1] = H1;
    } else {
        row[K2 + kq] = H0;     row[K2 + kq + 1] = H1;
        row[2 * K2 + kq] = L0; row[2 * K2 + kq + 1] = L1;
    }
}

// ---------------- fp32 [R][K] -> fp16 [R][2K] split -------------------------------
// amode=1 (A): [hi | lo]   amode=0 (B): [hi | hi]
__global__ __launch_bounds__(256) void cvt2(
    const float* __restrict__ x, __half* __restrict__ y, int K, int n4, int amode)
{
    int i = blockIdx.x * 256 + threadIdx.x;
    if (i >= n4) return;
    int e = i * 4;
    int r = e / K;
    int k = e - r * K;
    float4 v = *(const float4*)(x + (size_t)e);
    __half h0 = __float2half(v.x), h1 = __float2half(v.y);
    __half h2 = __float2half(v.z), h3 = __float2half(v.w);
    __half2 H0 = __halves2half2(h0, h1), H1 = __halves2half2(h2, h3);
    __half2 L0 = H0, L1 = H1;
    if (amode) {
        L0 = __halves2half2(__float2half(v.x - __half2float(h0)),
                            __float2half(v.y - __half2float(h1)));
        L1 = __halves2half2(__float2half(v.z - __half2float(h2)),
                            __float2half(v.w - __half2float(h3)));
    }
    __half2* row = (__half2*)(y + (size_t)r * 2 * K);
    int kq = k >> 1, K2 = K >> 1;
    row[kq] = H0;      row[kq + 1] = H1;
    row[K2 + kq] = L0; row[K2 + kq + 1] = L1;
}

// ---------------- fp16 mma.sync GEMM body: C[M,N] = A[M,Kd] * B[N,Kd]^T -----------
__device__ __forceinline__ uint32_t s2u(const void* p) {
    uint32_t a;
    asm("{ .reg .u64 t; cvta.to.shared.u64 t, %1; cvt.u32.u64 %0, t; }" : "=r"(a) : "l"(p));
    return a;
}

#define NSTAGE 4
#define ROWP 40                               // padded smem row: 40 fp16 = 80 B
#define STAGE_BYTES (128 * ROWP * 2)          // 10240
#define GEMM_SMEM (2 * NSTAGE * STAGE_BYTES)  // 81920

__device__ __forceinline__ void cp16(uint32_t s, const void* g) {
    asm volatile("cp.async.cg.shared.global [%0], [%1], 16;" :: "r"(s), "l"(g) : "memory");
}
__device__ __forceinline__ void ldmx4(uint32_t* r, uint32_t addr) {
    asm volatile("ldmatrix.sync.aligned.m8n8.x4.shared.b16 {%0,%1,%2,%3}, [%4];"
                 : "=r"(r[0]), "=r"(r[1]), "=r"(r[2]), "=r"(r[3]) : "r"(addr));
}
__device__ __forceinline__ void mma16816(float* d, const uint32_t* a, const uint32_t* b) {
    asm volatile(
        "mma.sync.aligned.m16n8k16.row.col.f32.f16.f16.f32 "
        "{%0,%1,%2,%3}, {%4,%5,%6,%7}, {%8,%9}, {%0,%1,%2,%3};"
        : "+f"(d[0]), "+f"(d[1]), "+f"(d[2]), "+f"(d[3])
        : "r"(a[0]), "r"(a[1]), "r"(a[2]), "r"(a[3]), "r"(b[0]), "r"(b[1]));
}

__device__ void gemm_body(
    const __half* __restrict__ A, const __half* __restrict__ B,
    float* __restrict__ C, int N, int Kd, int bx, int by, char* dsm)
{
    const uint32_t sb = s2u(dsm);
    const uint32_t sA = sb, sB = sb + NSTAGE * STAGE_BYTES;
    const int tid = threadIdx.x, lane = tid & 31, wid = tid >> 5;
    const int wm = wid & 1, wn = wid >> 1;        // warp grid 2 x 4
    const int rowB = by * 128, colB = bx * 128;

    const int lr = tid >> 1;
    const int ls = (tid & 1) * 16;
    const __half* gA = A + (size_t)(rowB + lr) * Kd + ls;
    const __half* gB = B + (size_t)(colB + lr) * Kd + ls;
    const uint32_t smA = sA + (uint32_t)(lr * ROWP + ls) * 2;
    const uint32_t smB = sB + (uint32_t)(lr * ROWP + ls) * 2;

    const int mid = lane >> 3;
    const int aRow = (lane & 7) + ((mid & 1) << 3);
    const int aK   = (mid >> 1) << 3;
    const uint32_t aBase = sA + (uint32_t)((wm * 64 + aRow) * ROWP + aK) * 2;
    const int bN = ((mid >> 1) << 3) + (lane & 7);
    const int bK = (mid & 1) << 3;
    const uint32_t bBase = sB + (uint32_t)((wn * 32 + bN) * ROWP + bK) * 2;

    float acc[4][4][4];
#pragma unroll
    for (int i = 0; i < 4; i++)
#pragma unroll
        for (int j = 0; j < 4; j++)
#pragma unroll
            for (int q = 0; q < 4; q++) acc[i][j][q] = 0.f;

    auto load_stage = [&](int kt) {
        uint32_t off = (uint32_t)(kt & (NSTAGE - 1)) * STAGE_BYTES;
        const __half* pa = gA + (size_t)kt * 32;
        const __half* pb = gB + (size_t)kt * 32;
        cp16(smA + off, pa);      cp16(smA + off + 16, pa + 8);
        cp16(smB + off, pb);      cp16(smB + off + 16, pb + 8);
    };

    const int NT = Kd >> 5;
    load_stage(0); asm volatile("cp.async.commit_group;" ::: "memory");
    load_stage(1); asm volatile("cp.async.commit_group;" ::: "memory");
    load_stage(2); asm volatile("cp.async.commit_group;" ::: "memory");

    for (int kt = 0; kt < NT; kt++) {
        asm volatile("cp.async.wait_group 2;" ::: "memory");
        __syncthreads();
        if (kt + 3 < NT) load_stage(kt + 3);
        asm volatile("cp.async.commit_group;" ::: "memory");

        const uint32_t soff = (uint32_t)(kt & (NSTAGE - 1)) * STAGE_BYTES;
#pragma unroll
        for (int kh = 0; kh < 2; kh++) {
            uint32_t ra[4][4], rb[2][4];
#pragma unroll
            for (int mt = 0; mt < 4; mt++)
                ldmx4(ra[mt], aBase + soff + (uint32_t)(mt * 16 * ROWP * 2) + kh * 32);
#pragma unroll
            for (int np = 0; np < 2; np++)
                ldmx4(rb[np], bBase + soff + (uint32_t)(np * 16 * ROWP * 2) + kh * 32);
#pragma unroll
            for (int mt = 0; mt < 4; mt++)
#pragma unroll
                for (int nt = 0; nt < 4; nt++)
                    mma16816(acc[mt][nt], ra[mt], &rb[nt >> 1][(nt & 1) * 2]);
        }
    }

    const int erow = rowB + wm * 64 + (lane >> 2);
    const int ecol = colB + wn * 32 + (lane & 3) * 2;
#pragma unroll
    for (int mt = 0; mt < 4; mt++) {
#pragma unroll
        for (int nt = 0; nt < 4; nt++) {
            float* p0 = C + (size_t)(erow + mt * 16) * N + ecol + nt * 8;
            *(float2*)p0                   = make_float2(acc[mt][nt][0], acc[mt][nt][1]);
            *(float2*)(p0 + (size_t)8 * N) = make_float2(acc[mt][nt][2], acc[mt][nt][3]);
        }
    }
}

__global__ __launch_bounds__(256) void gemm_mma(
    const __half* __restrict__ A, const __half* __restrict__ B,
    float* __restrict__ C, int N, int Kd)
{
    extern __shared__ char dsm[];
    gemm_body(A, B, C, N, Kd, blockIdx.x, blockIdx.y, dsm);
}

// ---------------- recurrence body (two dv-halves per 256-thread block) ------------
__device__ void rec_body()
{
    __shared__ float sq[128], sk[128], redA[256], redB[256], sgb[2];
    const int blk = blockIdx.x;          // 0..63
    const int h   = blk & 31;
    const int b   = blk >> 5;
    const int hk  = h >> 1;              // GQA repeat 2
    const int tid = threadIdx.x;
    const int vh  = tid >> 7;            // dv half
    const int wtid = tid & 127;
    const int dkh = wtid >> 6;
    const int dvl = wtid & 63;
    const int dv  = vh * 64 + dvl;
    const int dk0 = dkh * 64;

    float st[64];
#pragma unroll
    for (int i = 0; i < 64; i++) st[i] = 0.f;

    const float* qb = g_conv + (size_t)b * Ss * CONV_DIM + hk * 128;
    const float* kb = qb + KEY_DIM;
    const float* vb = g_conv + (size_t)b * Ss * CONV_DIM + 2 * KEY_DIM + h * 128 + dv;
    float*       ob = g_o    + (size_t)b * Ss * VAL_DIM + h * 128 + dv;
    const float* gp = g_dec  + (size_t)b * Ss * NVH + h;
    const float* bp = g_beta + (size_t)b * Ss * NVH + h;

    for (int t = 0; t < Ss; t++) {
        size_t off = (size_t)t * CONV_DIM;
        if (tid < 128) { sq[tid] = qb[off + tid]; sk[tid] = kb[off + tid]; }
        if (tid == 0) sgb[0] = gp[(size_t)t * NVH];
        if (tid == 1) sgb[1] = bp[(size_t)t * NVH];
        float v = vb[off];
        __syncthreads();                                   // S_a: tile visible
        float eg  = expf(sgb[0]);
        float bet = sgb[1];

        float m0 = 0.f, m1 = 0.f, m2 = 0.f, m3 = 0.f;
#pragma unroll
        for (int i = 0; i < 64; i += 4) {
            float s0 = st[i]     * eg;
            float s1 = st[i + 1] * eg;
            float s2 = st[i + 2] * eg;
            float s3 = st[i + 3] * eg;
            st[i] = s0; st[i + 1] = s1; st[i + 2] = s2; st[i + 3] = s3;
            m0 += sk[dk0 + i]     * s0;
            m1 += sk[dk0 + i + 1] * s1;
            m2 += sk[dk0 + i + 2] * s2;
            m3 += sk[dk0 + i + 3] * s3;
        }
        redA[tid] = (m0 + m1) + (m2 + m3);
        __syncthreads();                                   // S_b: partials visible
        float mem   = redA[tid] + redA[tid ^ 64];
        float delta = (v - mem) * bet;

        float o0 = 0.f, o1 = 0.f, o2 = 0.f, o3 = 0.f;
#pragma unroll
        for (int i = 0; i < 64; i += 4) {
            float s0 = st[i]     + sk[dk0 + i]     * delta;
            float s1 = st[i + 1] + sk[dk0 + i + 1] * delta;
            float s2 = st[i + 2] + sk[dk0 + i + 2] * delta;
            float s3 = st[i + 3] + sk[dk0 + i + 3] * delta;
            st[i] = s0; st[i + 1] = s1; st[i + 2] = s2; st[i + 3] = s3;
            o0 += sq[dk0 + i]     * s0;
            o1 += sq[dk0 + i + 1] * s1;
            o2 += sq[dk0 + i + 2] * s2;
            o3 += sq[dk0 + i + 3] * s3;
        }
        redB[tid] = (o0 + o1) + (o2 + o3);
        __syncthreads();                                   // S_c: o-partials visible
        if (dkh == 0) ob[(size_t)t * VAL_DIM] = redB[tid] + redB[tid ^ 64];
    }
}

// ---------------- fused: blocks 0..63 recurrence, 64.. GEMM2 tiles ----------------
__global__ __launch_bounds__(256) void fused_rec_gemm(
    const __half* __restrict__ A, const __half* __restrict__ B,
    float* __restrict__ C, int N, int Kd)
{
    extern __shared__ char dsm[];
    if (blockIdx.x < 64) {
        rec_body();
    } else {
        int g = blockIdx.x - 64;
        gemm_body(A, B, C, N, Kd, g & 31, g >> 5, dsm);
    }
}

// ---------------- causal depthwise conv (K=4) + silu ------------------------------
__global__ __launch_bounds__(256) void conv_silu(const float* __restrict__ w)
{
    size_t idx = (size_t)blockIdx.x * 256 + threadIdx.x;
    int c = (int)(idx & (CONV_DIM - 1));
    size_t bs = idx >> 13;
    int s = (int)(bs & (Ss - 1));
    const float* col = g_mixed + idx;
    float4 wv = *(const float4*)(w + (size_t)c * 4);
    float acc = wv.w * col[0];
    if (s >= 1) acc += wv.z * col[-(ptrdiff_t)CONV_DIM];
    if (s >= 2) acc += wv.y * col[-(ptrdiff_t)2 * CONV_DIM];
    if (s >= 3) acc += wv.x * col[-(ptrdiff_t)3 * CONV_DIM];
    g_conv[idx] = acc / (1.f + expf(-acc));
}

// ---------------- l2-normalize q,k heads in-place (q also gets DK^-0.5) -----------
__global__ __launch_bounds__(128) void l2norm_qk()
{
    int g = blockIdx.x & 31;
    size_t row = blockIdx.x >> 5;
    float* p = g_conv + row * CONV_DIM + (size_t)g * 128;
    float v = p[threadIdx.x];
    float ss = v * v;
    __shared__ float sh[4];
#pragma unroll
    for (int o = 16; o; o >>= 1) ss += __shfl_down_sync(0xffffffffu, ss, o);
    if ((threadIdx.x & 31) == 0) sh[threadIdx.x >> 5] = ss;
    __syncthreads();
    float tot = sh[0] + sh[1] + sh[2] + sh[3];
    float r = rsqrtf(tot + 1e-6f);
    if (g < 16) r *= 0.08838834764831845f;
    p[threadIdx.x] = v * r;
}

// ---------------- b/a projections -> beta, log-decay g ----------------------------
__global__ __launch_bounds__(128) void proj_bg(
    const float* __restrict__ hs, const float* __restrict__ Wb,
    const float* __restrict__ Wa, const float* __restrict__ dtb,
    const float* __restrict__ Alog)
{
    __shared__ float sh[HIDD];
    size_t row = blockIdx.x;
    const float* hr = hs + row * HIDD;
    for (int i = threadIdx.x; i < HIDD; i += 128) sh[i] = hr[i];
    __syncthreads();
    int warp = threadIdx.x >> 5, lane = threadIdx.x & 31;
    for (int i = 0; i < 16; i++) {
        int o = warp * 16 + i;
        const float* w = (o < 32) ? (Wb + (size_t)o * HIDD) : (Wa + (size_t)(o - 32) * HIDD);
        float s = 0.f;
        for (int k2 = lane; k2 < HIDD; k2 += 32) s += sh[k2] * w[k2];
#pragma unroll
        for (int off = 16; off; off >>= 1) s += __shfl_down_sync(0xffffffffu, s, off);
        if (lane == 0) {
            if (o < 32) {
                g_beta[row * NVH + o] = 1.f / (1.f + expf(-s));
            } else {
                int h = o - 32;
                float x = s + dtb[h];
                float sp = (x > 20.f) ? x : log1pf(expf(x));
                g_dec[row * NVH + h] = -expf(Alog[h]) * sp;
            }
        }
    }
}

// ---------------- gated RMSNorm: o = o*rsqrt(mean(o^2)+eps)*w * silu(z) -----------
__global__ __launch_bounds__(128) void gate_norm(const float* __restrict__ nw)
{
    size_t row = blockIdx.x;
    float* op = g_o + row * DVD;
    const float* zp = g_z + row * DVD;
    float v = op[threadIdx.x];
    float ss = v * v;
    __shared__ float sh[4];
#pragma unroll
    for (int o = 16; o; o >>= 1) ss += __shfl_down_sync(0xffffffffu, ss, o);
    if ((threadIdx.x & 31) == 0) sh[threadIdx.x >> 5] = ss;
    __syncthreads();
    float var = (sh[0] + sh[1] + sh[2] + sh[3]) * (1.f / DVD);
    float r = rsqrtf(var + 1e-6f);
    float z = zp[threadIdx.x];
    float sz = z / (1.f + expf(-z));
    op[threadIdx.x] = v * r * nw[threadIdx.x] * sz;
}

// ---------------- launch -----------------------------------------------------------
extern "C" void kernel_launch(void* const* d_in, const int* in_sizes, int n_in,
                              void* d_out, int out_size)
{
    const float* hs   = (const float*)d_in[0];
    const float* Wqkv = (const float*)d_in[1];
    const float* Wz   = (const float*)d_in[2];
    const float* Wb   = (const float*)d_in[3];
    const float* Wa   = (const float*)d_in[4];
    const float* cw   = (const float*)d_in[5];
    const float* nw   = (const float*)d_in[6];
    const float* Wout = (const float*)d_in[7];
    const float* dtb  = (const float*)d_in[8];
    const float* Alog = (const float*)d_in[9];
    float* out = (float*)d_out;

    float *mixed, *zb, *ob;
    __half *hs3, *wq3, *hs2, *wz2, *wo2, *go2;
    cudaGetSymbolAddress((void**)&mixed, g_mixed);
    cudaGetSymbolAddress((void**)&zb,    g_z);
    cudaGetSymbolAddress((void**)&ob,    g_o);
    cudaGetSymbolAddress((void**)&hs3, g_hs3);
    cudaGetSymbolAddress((void**)&wq3, g_wq3);
    cudaGetSymbolAddress((void**)&hs2, g_hs2);
    cudaGetSymbolAddress((void**)&wz2, g_wz2);
    cudaGetSymbolAddress((void**)&wo2, g_wo2);
    cudaGetSymbolAddress((void**)&go2, g_go2);

    cudaFuncSetAttribute(gemm_mma, cudaFuncAttributeMaxDynamicSharedMemorySize, GEMM_SMEM);
    cudaFuncSetAttribute(fused_rec_gemm, cudaFuncAttributeMaxDynamicSharedMemorySize, GEMM_SMEM);

    const int M = Bb * Ss;                                  // 4096

    // 0. fp16 splits
    cvt3<<<(M * HIDD / 4 + 255) / 256, 256>>>(hs, hs3, HIDD, M * HIDD / 4, 1);
    cvt3<<<(CONV_DIM * HIDD / 4 + 255) / 256, 256>>>(Wqkv, wq3, HIDD, CONV_DIM * HIDD / 4, 0);
    cvt2<<<(M * HIDD / 4 + 255) / 256, 256>>>(hs, hs2, HIDD, M * HIDD / 4, 1);
    cvt2<<<(VAL_DIM * HIDD / 4 + 255) / 256, 256>>>(Wz, wz2, HIDD, VAL_DIM * HIDD / 4, 0);
    cvt2<<<(HIDD * VAL_DIM / 4 + 255) / 256, 256>>>(Wout, wo2, VAL_DIM, HIDD * VAL_DIM / 4, 0);

    // 1. qkv projection (fp16x3 HMMA): [M,3H] x [CONV_DIM,3H]^T
    gemm_mma<<<dim3(CONV_DIM / 128, M / 128), 256, GEMM_SMEM>>>(
        hs3, wq3, mixed, CONV_DIM, 3 * HIDD);
    // 2. beta / log-decay
    proj_bg<<<M, 128>>>(hs, Wb, Wa, dtb, Alog);
    // 3. causal depthwise conv + silu
    conv_silu<<<(Bb * Ss * CONV_DIM) / 256, 256>>>(cw);
    // 4. l2norm q,k
    l2norm_qk<<<Bb * Ss * 32, 128>>>();
    // 5. FUSED: recurrence (blocks 0..63)  +  z-gate GEMM2 fp16x2 (blocks 64..1087)
    fused_rec_gemm<<<64 + (VAL_DIM / 128) * (M / 128), 256, GEMM_SMEM>>>(
        hs2, wz2, zb, VAL_DIM, 2 * HIDD);
    // 6. gated RMSNorm (in-place on g_o)
    gate_norm<<<Bb * Ss * NVH, 128>>>(nw);
    // 7. split gated output, then output projection fp16x2 -> d_out
    cvt2<<<(M * VAL_DIM / 4 + 255) / 256, 256>>>(ob, go2, VAL_DIM, M * VAL_DIM / 4, 1);
    gemm_mma<<<dim3(HIDD / 128, M / 128), 256, GEMM_SMEM>>>(
        go2, wo2, out, HIDD, 2 * VAL_DIM);
}

// round 16
// speedup vs baseline: 1.6698x; 1.5857x over previous
#include <cuda_runtime.h>
#include <cuda_fp16.h>
#include <math.h>
#include <stdint.h>

#define Bb 2
#define Ss 2048
#define HIDD 2048
#define NKH 16
#define NVH 32
#define DKD 128
#define DVD 128
#define KEY_DIM 2048
#define VAL_DIM 4096
#define CONV_DIM 8192

// ---------------- fp32 scratch ---------------------------------------------------
__device__ float g_mixed[(size_t)Bb * Ss * CONV_DIM];
__device__ float g_conv [(size_t)Bb * Ss * CONV_DIM];
__device__ float g_z    [(size_t)Bb * Ss * VAL_DIM];
__device__ float g_o    [(size_t)Bb * Ss * VAL_DIM];
__device__ float g_beta [Bb * Ss * NVH];
__device__ float g_dec  [Bb * Ss * NVH];

// ---------------- fp16 split scratch ([hi|lo] for A operands, [hi|hi] for B) ------
__device__ __half g_hs2[(size_t)4096 * 2 * 2048];   // hidden_states [h|l]  (GEMM1/2 A)
__device__ __half g_wq2[(size_t)8192 * 2 * 2048];   // W_qkv         [h|h]  (GEMM1 B)
__device__ __half g_wz2[(size_t)4096 * 2 * 2048];   // W_z           [h|h]  (GEMM2 B)
__device__ __half g_wo2[(size_t)2048 * 2 * 4096];   // W_out         [h|h]  (GEMM3 B)
__device__ __half g_go2[(size_t)4096 * 2 * 4096];   // gated output  [h|l]  (GEMM3 A)

// ---------------- fp32 [R][K] -> fp16 [R][2K] split -------------------------------
// amode=1 (A): [hi | lo]   amode=0 (B): [hi | hi]
__global__ __launch_bounds__(256) void cvt2(
    const float* __restrict__ x, __half* __restrict__ y, int K, int n4, int amode)
{
    int i = blockIdx.x * 256 + threadIdx.x;
    if (i >= n4) return;
    int e = i * 4;
    int r = e / K;
    int k = e - r * K;
    float4 v = *(const float4*)(x + (size_t)e);
    __half h0 = __float2half(v.x), h1 = __float2half(v.y);
    __half h2 = __float2half(v.z), h3 = __float2half(v.w);
    __half2 H0 = __halves2half2(h0, h1), H1 = __halves2half2(h2, h3);
    __half2 L0 = H0, L1 = H1;
    if (amode) {
        L0 = __halves2half2(__float2half(v.x - __half2float(h0)),
                            __float2half(v.y - __half2float(h1)));
        L1 = __halves2half2(__float2half(v.z - __half2float(h2)),
                            __float2half(v.w - __half2float(h3)));
    }
    __half2* row = (__half2*)(y + (size_t)r * 2 * K);
    int kq = k >> 1, K2 = K >> 1;
    row[kq] = H0;      row[kq + 1] = H1;
    row[K2 + kq] = L0; row[K2 + kq + 1] = L1;
}

// ---------------- fp16 mma.sync GEMM body: C[M,N] = A[M,Kd] * B[N,Kd]^T -----------
__device__ __forceinline__ uint32_t s2u(const void* p) {
    uint32_t a;
    asm("{ .reg .u64 t; cvta.to.shared.u64 t, %1; cvt.u32.u64 %0, t; }" : "=r"(a) : "l"(p));
    return a;
}

#define NSTAGE 4
#define ROWP 40                               // padded smem row: 40 fp16 = 80 B
#define STAGE_BYTES (128 * ROWP * 2)          // 10240
#define GEMM_SMEM (2 * NSTAGE * STAGE_BYTES)  // 81920

__device__ __forceinline__ void cp16(uint32_t s, const void* g) {
    asm volatile("cp.async.cg.shared.global [%0], [%1], 16;" :: "r"(s), "l"(g) : "memory");
}
__device__ __forceinline__ void ldmx4(uint32_t* r, uint32_t addr) {
    asm volatile("ldmatrix.sync.aligned.m8n8.x4.shared.b16 {%0,%1,%2,%3}, [%4];"
                 : "=r"(r[0]), "=r"(r[1]), "=r"(r[2]), "=r"(r[3]) : "r"(addr));
}
__device__ __forceinline__ void mma16816(float* d, const uint32_t* a, const uint32_t* b) {
    asm volatile(
        "mma.sync.aligned.m16n8k16.row.col.f32.f16.f16.f32 "
        "{%0,%1,%2,%3}, {%4,%5,%6,%7}, {%8,%9}, {%0,%1,%2,%3};"
        : "+f"(d[0]), "+f"(d[1]), "+f"(d[2]), "+f"(d[3])
        : "r"(a[0]), "r"(a[1]), "r"(a[2]), "r"(a[3]), "r"(b[0]), "r"(b[1]));
}

__device__ void gemm_body(
    const __half* __restrict__ A, const __half* __restrict__ B,
    float* __restrict__ C, int N, int Kd, int bx, int by, char* dsm)
{
    const uint32_t sb = s2u(dsm);
    const uint32_t sA = sb, sB = sb + NSTAGE * STAGE_BYTES;
    const int tid = threadIdx.x, lane = tid & 31, wid = tid >> 5;
    const int wm = wid & 1, wn = wid >> 1;        // warp grid 2 x 4
    const int rowB = by * 128, colB = bx * 128;

    const int lr = tid >> 1;
    const int ls = (tid & 1) * 16;
    const __half* gA = A + (size_t)(rowB + lr) * Kd + ls;
    const __half* gB = B + (size_t)(colB + lr) * Kd + ls;
    const uint32_t smA = sA + (uint32_t)(lr * ROWP + ls) * 2;
    const uint32_t smB = sB + (uint32_t)(lr * ROWP + ls) * 2;

    const int mid = lane >> 3;
    const int aRow = (lane & 7) + ((mid & 1) << 3);
    const int aK   = (mid >> 1) << 3;
    const uint32_t aBase = sA + (uint32_t)((wm * 64 + aRow) * ROWP + aK) * 2;
    const int bN = ((mid >> 1) << 3) + (lane & 7);
    const int bK = (mid & 1) << 3;
    const uint32_t bBase = sB + (uint32_t)((wn * 32 + bN) * ROWP + bK) * 2;

    float acc[4][4][4];
#pragma unroll
    for (int i = 0; i < 4; i++)
#pragma unroll
        for (int j = 0; j < 4; j++)
#pragma unroll
            for (int q = 0; q < 4; q++) acc[i][j][q] = 0.f;

    auto load_stage = [&](int kt) {
        uint32_t off = (uint32_t)(kt & (NSTAGE - 1)) * STAGE_BYTES;
        const __half* pa = gA + (size_t)kt * 32;
        const __half* pb = gB + (size_t)kt * 32;
        cp16(smA + off, pa);      cp16(smA + off + 16, pa + 8);
        cp16(smB + off, pb);      cp16(smB + off + 16, pb + 8);
    };

    const int NT = Kd >> 5;
    load_stage(0); asm volatile("cp.async.commit_group;" ::: "memory");
    load_stage(1); asm volatile("cp.async.commit_group;" ::: "memory");
    load_stage(2); asm volatile("cp.async.commit_group;" ::: "memory");

    for (int kt = 0; kt < NT; kt++) {
        asm volatile("cp.async.wait_group 2;" ::: "memory");
        __syncthreads();
        if (kt + 3 < NT) load_stage(kt + 3);
        asm volatile("cp.async.commit_group;" ::: "memory");

        const uint32_t soff = (uint32_t)(kt & (NSTAGE - 1)) * STAGE_BYTES;
#pragma unroll
        for (int kh = 0; kh < 2; kh++) {
            uint32_t ra[4][4], rb[2][4];
#pragma unroll
            for (int mt = 0; mt < 4; mt++)
                ldmx4(ra[mt], aBase + soff + (uint32_t)(mt * 16 * ROWP * 2) + kh * 32);
#pragma unroll
            for (int np = 0; np < 2; np++)
                ldmx4(rb[np], bBase + soff + (uint32_t)(np * 16 * ROWP * 2) + kh * 32);
#pragma unroll
            for (int mt = 0; mt < 4; mt++)
#pragma unroll
                for (int nt = 0; nt < 4; nt++)
                    mma16816(acc[mt][nt], ra[mt], &rb[nt >> 1][(nt & 1) * 2]);
        }
    }

    const int erow = rowB + wm * 64 + (lane >> 2);
    const int ecol = colB + wn * 32 + (lane & 3) * 2;
#pragma unroll
    for (int mt = 0; mt < 4; mt++) {
#pragma unroll
        for (int nt = 0; nt < 4; nt++) {
            float* p0 = C + (size_t)(erow + mt * 16) * N + ecol + nt * 8;
            *(float2*)p0                   = make_float2(acc[mt][nt][0], acc[mt][nt][1]);
            *(float2*)(p0 + (size_t)8 * N) = make_float2(acc[mt][nt][2], acc[mt][nt][3]);
        }
    }
}

__global__ __launch_bounds__(256) void gemm_mma(
    const __half* __restrict__ A, const __half* __restrict__ B,
    float* __restrict__ C, int N, int Kd)
{
    extern __shared__ char dsm[];
    gemm_body(A, B, C, N, Kd, blockIdx.x, blockIdx.y, dsm);
}

// ---------------- recurrence body: double-buffered, 2 barriers/step ---------------
__device__ void rec_body()
{
    __shared__ float sq[2][128], sk[2][128], redA[2][256], redB[2][256], sgb[2][2];
    const int blk = blockIdx.x;          // 0..63
    const int h   = blk & 31;
    const int b   = blk >> 5;
    const int hk  = h >> 1;              // GQA repeat 2
    const int tid = threadIdx.x;
    const int vh  = tid >> 7;            // dv half
    const int wtid = tid & 127;
    const int dkh = wtid >> 6;
    const int dvl = wtid & 63;
    const int dv  = vh * 64 + dvl;
    const int dk0 = dkh * 64;

    float st[64];
#pragma unroll
    for (int i = 0; i < 64; i++) st[i] = 0.f;

    const float* qb = g_conv + (size_t)b * Ss * CONV_DIM + hk * 128;
    const float* kb = qb + KEY_DIM;
    const float* vb = g_conv + (size_t)b * Ss * CONV_DIM + 2 * KEY_DIM + h * 128 + dv;
    float*       ob = g_o    + (size_t)b * Ss * VAL_DIM + h * 128 + dv;
    const float* gp = g_dec  + (size_t)b * Ss * NVH + h;
    const float* bp = g_beta + (size_t)b * Ss * NVH + h;

    // preload step 0
    if (tid < 128) { sq[0][tid] = qb[tid]; sk[0][tid] = kb[tid]; }
    if (tid == 0) sgb[0][0] = gp[0];
    if (tid == 1) sgb[0][1] = bp[0];
    float vcur = vb[0];
    __syncthreads();

    for (int t = 0; t < Ss; t++) {
        const int p = t & 1;
        float eg  = expf(sgb[p][0]);
        float bet = sgb[p][1];

        // prefetch step t+1 into registers (hidden under compute)
        float qn = 0.f, kn = 0.f, vn = 0.f, gn = 0.f, bn = 0.f;
        if (t + 1 < Ss) {
            size_t offn = (size_t)(t + 1) * CONV_DIM;
            if (tid < 128) { qn = qb[offn + tid]; kn = kb[offn + tid]; }
            vn = vb[offn];
            if (tid == 0) gn = gp[(size_t)(t + 1) * NVH];
            if (tid == 1) bn = bp[(size_t)(t + 1) * NVH];
        }

        float m0 = 0.f, m1 = 0.f, m2 = 0.f, m3 = 0.f;
#pragma unroll
        for (int i = 0; i < 64; i += 4) {
            float s0 = st[i]     * eg;
            float s1 = st[i + 1] * eg;
            float s2 = st[i + 2] * eg;
            float s3 = st[i + 3] * eg;
            st[i] = s0; st[i + 1] = s1; st[i + 2] = s2; st[i + 3] = s3;
            m0 += sk[p][dk0 + i]     * s0;
            m1 += sk[p][dk0 + i + 1] * s1;
            m2 += sk[p][dk0 + i + 2] * s2;
            m3 += sk[p][dk0 + i + 3] * s3;
        }
        redA[p][tid] = (m0 + m1) + (m2 + m3);
        __syncthreads();                               // B1: m-partials visible
        float mem   = redA[p][tid] + redA[p][tid ^ 64];
        float delta = (vcur - mem) * bet;

        float o0 = 0.f, o1 = 0.f, o2 = 0.f, o3 = 0.f;
#pragma unroll
        for (int i = 0; i < 64; i += 4) {
            float s0 = st[i]     + sk[p][dk0 + i]     * delta;
            float s1 = st[i + 1] + sk[p][dk0 + i + 1] * delta;
            float s2 = st[i + 2] + sk[p][dk0 + i + 2] * delta;
            float s3 = st[i + 3] + sk[p][dk0 + i + 3] * delta;
            st[i] = s0; st[i + 1] = s1; st[i + 2] = s2; st[i + 3] = s3;
            o0 += sq[p][dk0 + i]     * s0;
            o1 += sq[p][dk0 + i + 1] * s1;
            o2 += sq[p][dk0 + i + 2] * s2;
            o3 += sq[p][dk0 + i + 3] * s3;
        }
        redB[p][tid] = (o0 + o1) + (o2 + o3);
        if (t + 1 < Ss) {                              // stash prefetched tile
            if (tid < 128) { sq[p ^ 1][tid] = qn; sk[p ^ 1][tid] = kn; }
            if (tid == 0) sgb[p ^ 1][0] = gn;
            if (tid == 1) sgb[p ^ 1][1] = bn;
        }
        __syncthreads();                               // B2: o-partials + next tile
        if (dkh == 0) ob[(size_t)t * VAL_DIM] = redB[p][tid] + redB[p][tid ^ 64];
        vcur = vn;
    }
}

// ---------------- fused: blocks 0..63 recurrence, 64.. GEMM2 tiles ----------------
__global__ __launch_bounds__(256) void fused_rec_gemm(
    const __half* __restrict__ A, const __half* __restrict__ B,
    float* __restrict__ C, int N, int Kd)
{
    extern __shared__ char dsm[];
    if (blockIdx.x < 64) {
        rec_body();
    } else {
        int g = blockIdx.x - 64;
        gemm_body(A, B, C, N, Kd, g & 31, g >> 5, dsm);
    }
}

// ---------------- causal depthwise conv (K=4) + silu ------------------------------
__global__ __launch_bounds__(256) void conv_silu(const float* __restrict__ w)
{
    size_t idx = (size_t)blockIdx.x * 256 + threadIdx.x;
    int c = (int)(idx & (CONV_DIM - 1));
    size_t bs = idx >> 13;
    int s = (int)(bs & (Ss - 1));
    const float* col = g_mixed + idx;
    float4 wv = *(const float4*)(w + (size_t)c * 4);
    float acc = wv.w * col[0];
    if (s >= 1) acc += wv.z * col[-(ptrdiff_t)CONV_DIM];
    if (s >= 2) acc += wv.y * col[-(ptrdiff_t)2 * CONV_DIM];
    if (s >= 3) acc += wv.x * col[-(ptrdiff_t)3 * CONV_DIM];
    g_conv[idx] = acc / (1.f + expf(-acc));
}

// ---------------- l2-normalize q,k heads in-place (q also gets DK^-0.5) -----------
__global__ __launch_bounds__(128) void l2norm_qk()
{
    int g = blockIdx.x & 31;
    size_t row = blockIdx.x >> 5;
    float* p = g_conv + row * CONV_DIM + (size_t)g * 128;
    float v = p[threadIdx.x];
    float ss = v * v;
    __shared__ float sh[4];
#pragma unroll
    for (int o = 16; o; o >>= 1) ss += __shfl_down_sync(0xffffffffu, ss, o);
    if ((threadIdx.x & 31) == 0) sh[threadIdx.x >> 5] = ss;
    __syncthreads();
    float tot = sh[0] + sh[1] + sh[2] + sh[3];
    float r = rsqrtf(tot + 1e-6f);
    if (g < 16) r *= 0.08838834764831845f;
    p[threadIdx.x] = v * r;
}

// ---------------- b/a projections -> beta, log-decay g ----------------------------
__global__ __launch_bounds__(128) void proj_bg(
    const float* __restrict__ hs, const float* __restrict__ Wb,
    const float* __restrict__ Wa, const float* __restrict__ dtb,
    const float* __restrict__ Alog)
{
    __shared__ float sh[HIDD];
    size_t row = blockIdx.x;
    const float* hr = hs + row * HIDD;
    for (int i = threadIdx.x; i < HIDD; i += 128) sh[i] = hr[i];
    __syncthreads();
    int warp = threadIdx.x >> 5, lane = threadIdx.x & 31;
    for (int i = 0; i < 16; i++) {
        int o = warp * 16 + i;
        const float* w = (o < 32) ? (Wb + (size_t)o * HIDD) : (Wa + (size_t)(o - 32) * HIDD);
        float s = 0.f;
        for (int k2 = lane; k2 < HIDD; k2 += 32) s += sh[k2] * w[k2];
#pragma unroll
        for (int off = 16; off; off >>= 1) s += __shfl_down_sync(0xffffffffu, s, off);
        if (lane == 0) {
            if (o < 32) {
                g_beta[row * NVH + o] = 1.f / (1.f + expf(-s));
            } else {
                int h = o - 32;
                float x = s + dtb[h];
                float sp = (x > 20.f) ? x : log1pf(expf(x));
                g_dec[row * NVH + h] = -expf(Alog[h]) * sp;
            }
        }
    }
}

// ------- gated RMSNorm fused with fp16 [h|l] split of the GEMM3 A operand ---------
__global__ __launch_bounds__(128) void gate_norm_split(
    const float* __restrict__ nw, __half* __restrict__ go2)
{
    size_t row = blockIdx.x;                 // 0..B*S*NV-1
    const float* op = g_o + row * DVD;
    const float* zp = g_z + row * DVD;
    float v = op[threadIdx.x];
    float ss = v * v;
    __shared__ float sh[4];
#pragma unroll
    for (int o = 16; o; o >>= 1) ss += __shfl_down_sync(0xffffffffu, ss, o);
    if ((threadIdx.x & 31) == 0) sh[threadIdx.x >> 5] = ss;
    __syncthreads();
    float var = (sh[0] + sh[1] + sh[2] + sh[3]) * (1.f / DVD);
    float r = rsqrtf(var + 1e-6f);
    float z = zp[threadIdx.x];
    float sz = z / (1.f + expf(-z));
    float val = v * r * nw[threadIdx.x] * sz;
    __half hi = __float2half(val);
    __half lo = __float2half(val - __half2float(hi));
    size_t bs = row >> 5;                    // (b,s) index
    int hh = (int)(row & 31);
    size_t base = bs * (2 * VAL_DIM) + hh * 128 + threadIdx.x;
    go2[base] = hi;
    go2[base + VAL_DIM] = lo;
}

// ---------------- launch -----------------------------------------------------------
extern "C" void kernel_launch(void* const* d_in, const int* in_sizes, int n_in,
                              void* d_out, int out_size)
{
    const float* hs   = (const float*)d_in[0];
    const float* Wqkv = (const float*)d_in[1];
    const float* Wz   = (const float*)d_in[2];
    const float* Wb   = (const float*)d_in[3];
    const float* Wa   = (const float*)d_in[4];
    const float* cw   = (const float*)d_in[5];
    const float* nw   = (const float*)d_in[6];
    const float* Wout = (const float*)d_in[7];
    const float* dtb  = (const float*)d_in[8];
    const float* Alog = (const float*)d_in[9];
    float* out = (float*)d_out;

    float *mixed, *zb;
    __half *hs2, *wq2, *wz2, *wo2, *go2;
    cudaGetSymbolAddress((void**)&mixed, g_mixed);
    cudaGetSymbolAddress((void**)&zb,    g_z);
    cudaGetSymbolAddress((void**)&hs2, g_hs2);
    cudaGetSymbolAddress((void**)&wq2, g_wq2);
    cudaGetSymbolAddress((void**)&wz2, g_wz2);
    cudaGetSymbolAddress((void**)&wo2, g_wo2);
    cudaGetSymbolAddress((void**)&go2, g_go2);

    cudaFuncSetAttribute(gemm_mma, cudaFuncAttributeMaxDynamicSharedMemorySize, GEMM_SMEM);
    cudaFuncSetAttribute(fused_rec_gemm, cudaFuncAttributeMaxDynamicSharedMemorySize, GEMM_SMEM);

    const int M = Bb * Ss;                                  // 4096

    // 0. fp16 splits
    cvt2<<<(M * HIDD / 4 + 255) / 256, 256>>>(hs, hs2, HIDD, M * HIDD / 4, 1);
    cvt2<<<(CONV_DIM * HIDD / 4 + 255) / 256, 256>>>(Wqkv, wq2, HIDD, CONV_DIM * HIDD / 4, 0);
    cvt2<<<(VAL_DIM * HIDD / 4 + 255) / 256, 256>>>(Wz, wz2, HIDD, VAL_DIM * HIDD / 4, 0);
    cvt2<<<(HIDD * VAL_DIM / 4 + 255) / 256, 256>>>(Wout, wo2, VAL_DIM, HIDD * VAL_DIM / 4, 0);

    // 1. qkv projection (fp16x2 HMMA): [M,2H] x [CONV_DIM,2H]^T
    gemm_mma<<<dim3(CONV_DIM / 128, M / 128), 256, GEMM_SMEM>>>(
        hs2, wq2, mixed, CONV_DIM, 2 * HIDD);
    // 2. beta / log-decay
    proj_bg<<<M, 128>>>(hs, Wb, Wa, dtb, Alog);
    // 3. causal depthwise conv + silu
    conv_silu<<<(Bb * Ss * CONV_DIM) / 256, 256>>>(cw);
    // 4. l2norm q,k
    l2norm_qk<<<Bb * Ss * 32, 128>>>();
    // 5. FUSED: recurrence (blocks 0..63) + z-gate GEMM2 fp16x2 (blocks 64..1087)
    fused_rec_gemm<<<64 + (VAL_DIM / 128) * (M / 128), 256, GEMM_SMEM>>>(
        hs2, wz2, zb, VAL_DIM, 2 * HIDD);
    // 6. gated RMSNorm + fp16 [h|l] split (writes GEMM3's A operand directly)
    gate_norm_split<<<Bb * Ss * NVH, 128>>>(nw, go2);
    // 7. output projection fp16x2 -> d_out
    gemm_mma<<<dim3(HIDD / 128, M / 128), 256, GEMM_SMEM>>>(
        go2, wo2, out, HIDD, 2 * VAL_DIM);
}

// round 17
// speedup vs baseline: 1.6716x; 1.0010x over previous
#include <cuda_runtime.h>
#include <cuda_fp16.h>
#include <math.h>
#include <stdint.h>

#define Bb 2
#define Ss 2048
#define HIDD 2048
#define NKH 16
#define NVH 32
#define DKD 128
#define DVD 128
#define KEY_DIM 2048
#define VAL_DIM 4096
#define CONV_DIM 8192

// ---------------- fp32 scratch ---------------------------------------------------
__device__ float g_mixed[(size_t)Bb * Ss * CONV_DIM];
__device__ float g_conv [(size_t)Bb * Ss * CONV_DIM];
__device__ float g_z    [(size_t)Bb * Ss * VAL_DIM];
__device__ float g_o    [(size_t)Bb * Ss * VAL_DIM];
__device__ float g_beta [Bb * Ss * NVH];
__device__ float g_dec  [Bb * Ss * NVH];

// ---------------- fp16 split scratch ([hi|lo] for A operands, [hi|hi] for B) ------
__device__ __half g_hs2[(size_t)4096 * 2 * 2048];   // hidden_states [h|l]  (GEMM1/2 A)
__device__ __half g_wq2[(size_t)8192 * 2 * 2048];   // W_qkv         [h|h]  (GEMM1 B)
__device__ __half g_wz2[(size_t)4096 * 2 * 2048];   // W_z           [h|h]  (GEMM2 B)
__device__ __half g_wo2[(size_t)2048 * 2 * 4096];   // W_out         [h|h]  (GEMM3 B)
__device__ __half g_go2[(size_t)4096 * 2 * 4096];   // gated output  [h|l]  (GEMM3 A)

// ---------------- fp32 [R][K] -> fp16 [R][2K] split -------------------------------
// amode=1 (A): [hi | lo]   amode=0 (B): [hi | hi]
__global__ __launch_bounds__(256) void cvt2(
    const float* __restrict__ x, __half* __restrict__ y, int K, int n4, int amode)
{
    int i = blockIdx.x * 256 + threadIdx.x;
    if (i >= n4) return;
    int e = i * 4;
    int r = e / K;
    int k = e - r * K;
    float4 v = *(const float4*)(x + (size_t)e);
    __half h0 = __float2half(v.x), h1 = __float2half(v.y);
    __half h2 = __float2half(v.z), h3 = __float2half(v.w);
    __half2 H0 = __halves2half2(h0, h1), H1 = __halves2half2(h2, h3);
    __half2 L0 = H0, L1 = H1;
    if (amode) {
        L0 = __halves2half2(__float2half(v.x - __half2float(h0)),
                            __float2half(v.y - __half2float(h1)));
        L1 = __halves2half2(__float2half(v.z - __half2float(h2)),
                            __float2half(v.w - __half2float(h3)));
    }
    __half2* row = (__half2*)(y + (size_t)r * 2 * K);
    int kq = k >> 1, K2 = K >> 1;
    row[kq] = H0;      row[kq + 1] = H1;
    row[K2 + kq] = L0; row[K2 + kq + 1] = L1;
}

// ---------------- fp16 mma.sync GEMM body: C[M,N] = A[M,Kd] * B[N,Kd]^T -----------
__device__ __forceinline__ uint32_t s2u(const void* p) {
    uint32_t a;
    asm("{ .reg .u64 t; cvta.to.shared.u64 t, %1; cvt.u32.u64 %0, t; }" : "=r"(a) : "l"(p));
    return a;
}

#define NSTAGE 4
#define ROWP 40                               // padded smem row: 40 fp16 = 80 B
#define STAGE_BYTES (128 * ROWP * 2)          // 10240
#define GEMM_SMEM (2 * NSTAGE * STAGE_BYTES)  // 81920

__device__ __forceinline__ void cp16(uint32_t s, const void* g) {
    asm volatile("cp.async.cg.shared.global [%0], [%1], 16;" :: "r"(s), "l"(g) : "memory");
}
__device__ __forceinline__ void ldmx4(uint32_t* r, uint32_t addr) {
    asm volatile("ldmatrix.sync.aligned.m8n8.x4.shared.b16 {%0,%1,%2,%3}, [%4];"
                 : "=r"(r[0]), "=r"(r[1]), "=r"(r[2]), "=r"(r[3]) : "r"(addr));
}
__device__ __forceinline__ void mma16816(float* d, const uint32_t* a, const uint32_t* b) {
    asm volatile(
        "mma.sync.aligned.m16n8k16.row.col.f32.f16.f16.f32 "
        "{%0,%1,%2,%3}, {%4,%5,%6,%7}, {%8,%9}, {%0,%1,%2,%3};"
        : "+f"(d[0]), "+f"(d[1]), "+f"(d[2]), "+f"(d[3])
        : "r"(a[0]), "r"(a[1]), "r"(a[2]), "r"(a[3]), "r"(b[0]), "r"(b[1]));
}

__device__ void gemm_body(
    const __half* __restrict__ A, const __half* __restrict__ B,
    float* __restrict__ C, int N, int Kd, int bx, int by, char* dsm)
{
    const uint32_t sb = s2u(dsm);
    const uint32_t sA = sb, sB = sb + NSTAGE * STAGE_BYTES;
    const int tid = threadIdx.x, lane = tid & 31, wid = tid >> 5;
    const int wm = wid & 1, wn = wid >> 1;        // warp grid 2 x 4
    const int rowB = by * 128, colB = bx * 128;

    const int lr = tid >> 1;
    const int ls = (tid & 1) * 16;
    const __half* gA = A + (size_t)(rowB + lr) * Kd + ls;
    const __half* gB = B + (size_t)(colB + lr) * Kd + ls;
    const uint32_t smA = sA + (uint32_t)(lr * ROWP + ls) * 2;
    const uint32_t smB = sB + (uint32_t)(lr * ROWP + ls) * 2;

    const int mid = lane >> 3;
    const int aRow = (lane & 7) + ((mid & 1) << 3);
    const int aK   = (mid >> 1) << 3;
    const uint32_t aBase = sA + (uint32_t)((wm * 64 + aRow) * ROWP + aK) * 2;
    const int bN = ((mid >> 1) << 3) + (lane & 7);
    const int bK = (mid & 1) << 3;
    const uint32_t bBase = sB + (uint32_t)((wn * 32 + bN) * ROWP + bK) * 2;

    float acc[4][4][4];
#pragma unroll
    for (int i = 0; i < 4; i++)
#pragma unroll
        for (int j = 0; j < 4; j++)
#pragma unroll
            for (int q = 0; q < 4; q++) acc[i][j][q] = 0.f;

    auto load_stage = [&](int kt) {
        uint32_t off = (uint32_t)(kt & (NSTAGE - 1)) * STAGE_BYTES;
        const __half* pa = gA + (size_t)kt * 32;
        const __half* pb = gB + (size_t)kt * 32;
        cp16(smA + off, pa);      cp16(smA + off + 16, pa + 8);
        cp16(smB + off, pb);      cp16(smB + off + 16, pb + 8);
    };

    const int NT = Kd >> 5;
    load_stage(0); asm volatile("cp.async.commit_group;" ::: "memory");
    load_stage(1); asm volatile("cp.async.commit_group;" ::: "memory");
    load_stage(2); asm volatile("cp.async.commit_group;" ::: "memory");

    for (int kt = 0; kt < NT; kt++) {
        asm volatile("cp.async.wait_group 2;" ::: "memory");
        __syncthreads();
        if (kt + 3 < NT) load_stage(kt + 3);
        asm volatile("cp.async.commit_group;" ::: "memory");

        const uint32_t soff = (uint32_t)(kt & (NSTAGE - 1)) * STAGE_BYTES;
#pragma unroll
        for (int kh = 0; kh < 2; kh++) {
            uint32_t ra[4][4], rb[2][4];
#pragma unroll
            for (int mt = 0; mt < 4; mt++)
                ldmx4(ra[mt], aBase + soff + (uint32_t)(mt * 16 * ROWP * 2) + kh * 32);
#pragma unroll
            for (int np = 0; np < 2; np++)
                ldmx4(rb[np], bBase + soff + (uint32_t)(np * 16 * ROWP * 2) + kh * 32);
#pragma unroll
            for (int mt = 0; mt < 4; mt++)
#pragma unroll
                for (int nt = 0; nt < 4; nt++)
                    mma16816(acc[mt][nt], ra[mt], &rb[nt >> 1][(nt & 1) * 2]);
        }
    }

    const int erow = rowB + wm * 64 + (lane >> 2);
    const int ecol = colB + wn * 32 + (lane & 3) * 2;
#pragma unroll
    for (int mt = 0; mt < 4; mt++) {
#pragma unroll
        for (int nt = 0; nt < 4; nt++) {
            float* p0 = C + (size_t)(erow + mt * 16) * N + ecol + nt * 8;
            *(float2*)p0                   = make_float2(acc[mt][nt][0], acc[mt][nt][1]);
            *(float2*)(p0 + (size_t)8 * N) = make_float2(acc[mt][nt][2], acc[mt][nt][3]);
        }
    }
}

__global__ __launch_bounds__(256) void gemm_mma(
    const __half* __restrict__ A, const __half* __restrict__ B,
    float* __restrict__ C, int N, int Kd)
{
    extern __shared__ char dsm[];
    gemm_body(A, B, C, N, Kd, blockIdx.x, blockIdx.y, dsm);
}

// ---------------- recurrence body: double-buffered, 2 barriers/step ---------------
__device__ void rec_body()
{
    __shared__ float sq[2][128], sk[2][128], redA[2][256], redB[2][256], sgb[2][2];
    const int blk = blockIdx.x;          // 0..63
    const int h   = blk & 31;
    const int b   = blk >> 5;
    const int hk  = h >> 1;              // GQA repeat 2
    const int tid = threadIdx.x;
    const int vh  = tid >> 7;            // dv half
    const int wtid = tid & 127;
    const int dkh = wtid >> 6;
    const int dvl = wtid & 63;
    const int dv  = vh * 64 + dvl;
    const int dk0 = dkh * 64;

    float st[64];
#pragma unroll
    for (int i = 0; i < 64; i++) st[i] = 0.f;

    const float* qb = g_conv + (size_t)b * Ss * CONV_DIM + hk * 128;
    const float* kb = qb + KEY_DIM;
    const float* vb = g_conv + (size_t)b * Ss * CONV_DIM + 2 * KEY_DIM + h * 128 + dv;
    float*       ob = g_o    + (size_t)b * Ss * VAL_DIM + h * 128 + dv;
    const float* gp = g_dec  + (size_t)b * Ss * NVH + h;
    const float* bp = g_beta + (size_t)b * Ss * NVH + h;

    // preload step 0
    if (tid < 128) { sq[0][tid] = qb[tid]; sk[0][tid] = kb[tid]; }
    if (tid == 0) sgb[0][0] = gp[0];
    if (tid == 1) sgb[0][1] = bp[0];
    float vcur = vb[0];
    __syncthreads();

    for (int t = 0; t < Ss; t++) {
        const int p = t & 1;
        float eg  = expf(sgb[p][0]);
        float bet = sgb[p][1];

        // prefetch step t+1 into registers (hidden under compute)
        float qn = 0.f, kn = 0.f, vn = 0.f, gn = 0.f, bn = 0.f;
        if (t + 1 < Ss) {
            size_t offn = (size_t)(t + 1) * CONV_DIM;
            if (tid < 128) { qn = qb[offn + tid]; kn = kb[offn + tid]; }
            vn = vb[offn];
            if (tid == 0) gn = gp[(size_t)(t + 1) * NVH];
            if (tid == 1) bn = bp[(size_t)(t + 1) * NVH];
        }

        float m0 = 0.f, m1 = 0.f, m2 = 0.f, m3 = 0.f;
#pragma unroll
        for (int i = 0; i < 64; i += 4) {
            float s0 = st[i]     * eg;
            float s1 = st[i + 1] * eg;
            float s2 = st[i + 2] * eg;
            float s3 = st[i + 3] * eg;
            st[i] = s0; st[i + 1] = s1; st[i + 2] = s2; st[i + 3] = s3;
            m0 += sk[p][dk0 + i]     * s0;
            m1 += sk[p][dk0 + i + 1] * s1;
            m2 += sk[p][dk0 + i + 2] * s2;
            m3 += sk[p][dk0 + i + 3] * s3;
        }
        redA[p][tid] = (m0 + m1) + (m2 + m3);
        __syncthreads();                               // B1: m-partials visible
        float mem   = redA[p][tid] + redA[p][tid ^ 64];
        float delta = (vcur - mem) * bet;

        float o0 = 0.f, o1 = 0.f, o2 = 0.f, o3 = 0.f;
#pragma unroll
        for (int i = 0; i < 64; i += 4) {
            float s0 = st[i]     + sk[p][dk0 + i]     * delta;
            float s1 = st[i + 1] + sk[p][dk0 + i + 1] * delta;
            float s2 = st[i + 2] + sk[p][dk0 + i + 2] * delta;
            float s3 = st[i + 3] + sk[p][dk0 + i + 3] * delta;
            st[i] = s0; st[i + 1] = s1; st[i + 2] = s2; st[i + 3] = s3;
            o0 += sq[p][dk0 + i]     * s0;
            o1 += sq[p][dk0 + i + 1] * s1;
            o2 += sq[p][dk0 + i + 2] * s2;
            o3 += sq[p][dk0 + i + 3] * s3;
        }
        redB[p][tid] = (o0 + o1) + (o2 + o3);
        if (t + 1 < Ss) {                              // stash prefetched tile
            if (tid < 128) { sq[p ^ 1][tid] = qn; sk[p ^ 1][tid] = kn; }
            if (tid == 0) sgb[p ^ 1][0] = gn;
            if (tid == 1) sgb[p ^ 1][1] = bn;
        }
        __syncthreads();                               // B2: o-partials + next tile
        if (dkh == 0) ob[(size_t)t * VAL_DIM] = redB[p][tid] + redB[p][tid ^ 64];
        vcur = vn;
    }
}

// ---------------- fused: blocks 0..63 recurrence, 64.. GEMM2 tiles ----------------
__global__ __launch_bounds__(256) void fused_rec_gemm(
    const __half* __restrict__ A, const __half* __restrict__ B,
    float* __restrict__ C, int N, int Kd)
{
    extern __shared__ char dsm[];
    if (blockIdx.x < 64) {
        rec_body();
    } else {
        int g = blockIdx.x - 64;
        gemm_body(A, B, C, N, Kd, g & 31, g >> 5, dsm);
    }
}

// ---------------- causal depthwise conv (K=4) + silu ------------------------------
__global__ __launch_bounds__(256) void conv_silu(const float* __restrict__ w)
{
    size_t idx = (size_t)blockIdx.x * 256 + threadIdx.x;
    int c = (int)(idx & (CONV_DIM - 1));
    size_t bs = idx >> 13;
    int s = (int)(bs & (Ss - 1));
    const float* col = g_mixed + idx;
    float4 wv = *(const float4*)(w + (size_t)c * 4);
    float acc = wv.w * col[0];
    if (s >= 1) acc += wv.z * col[-(ptrdiff_t)CONV_DIM];
    if (s >= 2) acc += wv.y * col[-(ptrdiff_t)2 * CONV_DIM];
    if (s >= 3) acc += wv.x * col[-(ptrdiff_t)3 * CONV_DIM];
    g_conv[idx] = acc / (1.f + expf(-acc));
}

// ---------------- l2-normalize q,k heads in-place (q also gets DK^-0.5) -----------
__global__ __launch_bounds__(128) void l2norm_qk()
{
    int g = blockIdx.x & 31;
    size_t row = blockIdx.x >> 5;
    float* p = g_conv + row * CONV_DIM + (size_t)g * 128;
    float v = p[threadIdx.x];
    float ss = v * v;
    __shared__ float sh[4];
#pragma unroll
    for (int o = 16; o; o >>= 1) ss += __shfl_down_sync(0xffffffffu, ss, o);
    if ((threadIdx.x & 31) == 0) sh[threadIdx.x >> 5] = ss;
    __syncthreads();
    float tot = sh[0] + sh[1] + sh[2] + sh[3];
    float r = rsqrtf(tot + 1e-6f);
    if (g < 16) r *= 0.08838834764831845f;
    p[threadIdx.x] = v * r;
}

// ---------------- b/a projections -> beta, log-decay g ----------------------------
__global__ __launch_bounds__(128) void proj_bg(
    const float* __restrict__ hs, const float* __restrict__ Wb,
    const float* __restrict__ Wa, const float* __restrict__ dtb,
    const float* __restrict__ Alog)
{
    __shared__ float sh[HIDD];
    size_t row = blockIdx.x;
    const float* hr = hs + row * HIDD;
    for (int i = threadIdx.x; i < HIDD; i += 128) sh[i] = hr[i];
    __syncthreads();
    int warp = threadIdx.x >> 5, lane = threadIdx.x & 31;
    for (int i = 0; i < 16; i++) {
        int o = warp * 16 + i;
        const float* w = (o < 32) ? (Wb + (size_t)o * HIDD) : (Wa + (size_t)(o - 32) * HIDD);
        float s = 0.f;
        for (int k2 = lane; k2 < HIDD; k2 += 32) s += sh[k2] * w[k2];
#pragma unroll
        for (int off = 16; off; off >>= 1) s += __shfl_down_sync(0xffffffffu, s, off);
        if (lane == 0) {
            if (o < 32) {
                g_beta[row * NVH + o] = 1.f / (1.f + expf(-s));
            } else {
                int h = o - 32;
                float x = s + dtb[h];
                float sp = (x > 20.f) ? x : log1pf(expf(x));
                g_dec[row * NVH + h] = -expf(Alog[h]) * sp;
            }
        }
    }
}

// ------- gated RMSNorm fused with fp16 [h|l] split of the GEMM3 A operand ---------
__global__ __launch_bounds__(128) void gate_norm_split(
    const float* __restrict__ nw, __half* __restrict__ go2)
{
    size_t row = blockIdx.x;                 // 0..B*S*NV-1
    const float* op = g_o + row * DVD;
    const float* zp = g_z + row * DVD;
    float v = op[threadIdx.x];
    float ss = v * v;
    __shared__ float sh[4];
#pragma unroll
    for (int o = 16; o; o >>= 1) ss += __shfl_down_sync(0xffffffffu, ss, o);
    if ((threadIdx.x & 31) == 0) sh[threadIdx.x >> 5] = ss;
    __syncthreads();
    float var = (sh[0] + sh[1] + sh[2] + sh[3]) * (1.f / DVD);
    float r = rsqrtf(var + 1e-6f);
    float z = zp[threadIdx.x];
    float sz = z / (1.f + expf(-z));
    float val = v * r * nw[threadIdx.x] * sz;
    __half hi = __float2half(val);
    __half lo = __float2half(val - __half2float(hi));
    size_t bs = row >> 5;                    // (b,s) index
    int hh = (int)(row & 31);
    size_t base = bs * (2 * VAL_DIM) + hh * 128 + threadIdx.x;
    go2[base] = hi;
    go2[base + VAL_DIM] = lo;
}

// ---------------- launch -----------------------------------------------------------
extern "C" void kernel_launch(void* const* d_in, const int* in_sizes, int n_in,
                              void* d_out, int out_size)
{
    const float* hs   = (const float*)d_in[0];
    const float* Wqkv = (const float*)d_in[1];
    const float* Wz   = (const float*)d_in[2];
    const float* Wb   = (const float*)d_in[3];
    const float* Wa   = (const float*)d_in[4];
    const float* cw   = (const float*)d_in[5];
    const float* nw   = (const float*)d_in[6];
    const float* Wout = (const float*)d_in[7];
    const float* dtb  = (const float*)d_in[8];
    const float* Alog = (const float*)d_in[9];
    float* out = (float*)d_out;

    float *mixed, *zb;
    __half *hs2, *wq2, *wz2, *wo2, *go2;
    cudaGetSymbolAddress((void**)&mixed, g_mixed);
    cudaGetSymbolAddress((void**)&zb,    g_z);
    cudaGetSymbolAddress((void**)&hs2, g_hs2);
    cudaGetSymbolAddress((void**)&wq2, g_wq2);
    cudaGetSymbolAddress((void**)&wz2, g_wz2);
    cudaGetSymbolAddress((void**)&wo2, g_wo2);
    cudaGetSymbolAddress((void**)&go2, g_go2);

    cudaFuncSetAttribute(gemm_mma, cudaFuncAttributeMaxDynamicSharedMemorySize, GEMM_SMEM);
    cudaFuncSetAttribute(fused_rec_gemm, cudaFuncAttributeMaxDynamicSharedMemorySize, GEMM_SMEM);

    const int M = Bb * Ss;                                  // 4096

    // 0. fp16 splits
    cvt2<<<(M * HIDD / 4 + 255) / 256, 256>>>(hs, hs2, HIDD, M * HIDD / 4, 1);
    cvt2<<<(CONV_DIM * HIDD / 4 + 255) / 256, 256>>>(Wqkv, wq2, HIDD, CONV_DIM * HIDD / 4, 0);
    cvt2<<<(VAL_DIM * HIDD / 4 + 255) / 256, 256>>>(Wz, wz2, HIDD, VAL_DIM * HIDD / 4, 0);
    cvt2<<<(HIDD * VAL_DIM / 4 + 255) / 256, 256>>>(Wout, wo2, VAL_DIM, HIDD * VAL_DIM / 4, 0);

    // 1. qkv projection (fp16x2 HMMA): [M,2H] x [CONV_DIM,2H]^T
    gemm_mma<<<dim3(CONV_DIM / 128, M / 128), 256, GEMM_SMEM>>>(
        hs2, wq2, mixed, CONV_DIM, 2 * HIDD);
    // 2. beta / log-decay
    proj_bg<<<M, 128>>>(hs, Wb, Wa, dtb, Alog);
    // 3. causal depthwise conv + silu
    conv_silu<<<(Bb * Ss * CONV_DIM) / 256, 256>>>(cw);
    // 4. l2norm q,k
    l2norm_qk<<<Bb * Ss * 32, 128>>>();
    // 5. FUSED: recurrence (blocks 0..63) + z-gate GEMM2 fp16x2 (blocks 64..1087)
    fused_rec_gemm<<<64 + (VAL_DIM / 128) * (M / 128), 256, GEMM_SMEM>>>(
        hs2, wz2, zb, VAL_DIM, 2 * HIDD);
    // 6. gated RMSNorm + fp16 [h|l] split (writes GEMM3's A operand directly)
    gate_norm_split<<<Bb * Ss * NVH, 128>>>(nw, go2);
    // 7. output projection fp16x2 -> d_out
    gemm_mma<<<dim3(HIDD / 128, M / 128), 256, GEMM_SMEM>>>(
        go2, wo2, out, HIDD, 2 * VAL_DIM);
}